// round 1
// baseline (speedup 1.0000x reference)
#include <cuda_runtime.h>
#include <math.h>

// Shapes (fixed): B=16, N=1024, C=768, H=12, hd=64
#define DIMK 768
#define NTOK 16384            // 16*1024
#define HEADS 12

// ---------------- scratch (no cudaMalloc allowed) ----------------
__device__ __align__(16) float g_q[12582912];   // [B*H][1024][64], pre-scaled by 0.125
__device__ __align__(16) float g_k[12582912];   // [B*H][1024][64]
__device__ __align__(16) float g_v[12582912];   // [B*H][1024][64]
__device__ __align__(16) float g_ao[12582912];  // [B*N][768] attention output

// ---------------- GEMM config ----------------
#define BM 128
#define BN 64
#define BK 16
#define LDA_S 132   // padded stride for As[BK][BM]
#define LDB_S 68    // padded stride for Bs[BK][BN]

// C[m][n] = sum_k A[m][k]*W[n][k] + bias[n]   (both A and W are K-major, K=768)
// Thread block: 256 threads (16x16), each thread computes 8x4 outputs.

__global__ __launch_bounds__(256, 2)
void gemm_qkv_kernel(const float* __restrict__ X, const float* __restrict__ W,
                     const float* __restrict__ bias)
{
    __shared__ float As[BK * LDA_S];
    __shared__ float Bs[BK * LDB_S];

    const int tid = threadIdx.x;
    const int tx = tid & 15;
    const int ty = tid >> 4;
    const int bm = blockIdx.y;
    const int bn = blockIdx.x;

    const float* Ag = X + (size_t)bm * BM * DIMK;
    const float* Wg = W + (size_t)bn * BN * DIMK;

    const int lRow = tid >> 2;          // 0..63
    const int lCol = (tid & 3) * 4;     // 0,4,8,12

    // prefetch k-tile 0 into registers
    float4 aReg0 = *(const float4*)(Ag + (size_t)lRow * DIMK + lCol);
    float4 aReg1 = *(const float4*)(Ag + (size_t)(lRow + 64) * DIMK + lCol);
    float4 wReg  = *(const float4*)(Wg + (size_t)lRow * DIMK + lCol);

    float acc[8][4];
#pragma unroll
    for (int i = 0; i < 8; i++)
#pragma unroll
        for (int j = 0; j < 4; j++) acc[i][j] = 0.f;

    for (int kt = 0; kt < DIMK; kt += BK) {
        __syncthreads();
        // scatter-store transposed: As[k][m], Bs[k][n]
        As[(lCol + 0) * LDA_S + lRow] = aReg0.x;
        As[(lCol + 1) * LDA_S + lRow] = aReg0.y;
        As[(lCol + 2) * LDA_S + lRow] = aReg0.z;
        As[(lCol + 3) * LDA_S + lRow] = aReg0.w;
        As[(lCol + 0) * LDA_S + lRow + 64] = aReg1.x;
        As[(lCol + 1) * LDA_S + lRow + 64] = aReg1.y;
        As[(lCol + 2) * LDA_S + lRow + 64] = aReg1.z;
        As[(lCol + 3) * LDA_S + lRow + 64] = aReg1.w;
        Bs[(lCol + 0) * LDB_S + lRow] = wReg.x;
        Bs[(lCol + 1) * LDB_S + lRow] = wReg.y;
        Bs[(lCol + 2) * LDB_S + lRow] = wReg.z;
        Bs[(lCol + 3) * LDB_S + lRow] = wReg.w;
        __syncthreads();

        if (kt + BK < DIMK) {
            const int k2 = kt + BK;
            aReg0 = *(const float4*)(Ag + (size_t)lRow * DIMK + k2 + lCol);
            aReg1 = *(const float4*)(Ag + (size_t)(lRow + 64) * DIMK + k2 + lCol);
            wReg  = *(const float4*)(Wg + (size_t)lRow * DIMK + k2 + lCol);
        }

#pragma unroll
        for (int kk = 0; kk < BK; kk++) {
            float4 a0 = *(float4*)&As[kk * LDA_S + ty * 8];
            float4 a1 = *(float4*)&As[kk * LDA_S + ty * 8 + 4];
            float4 b0 = *(float4*)&Bs[kk * LDB_S + tx * 4];
            float a[8] = {a0.x, a0.y, a0.z, a0.w, a1.x, a1.y, a1.z, a1.w};
            float b[4] = {b0.x, b0.y, b0.z, b0.w};
#pragma unroll
            for (int i = 0; i < 8; i++)
#pragma unroll
                for (int j = 0; j < 4; j++)
                    acc[i][j] = fmaf(a[i], b[j], acc[i][j]);
        }
    }

    // epilogue: split into Q/K/V scratch [B*H][1024][64]; scale Q by hd^-0.5
    const int colBase = bn * BN;               // multiple of 64
    const int which = colBase / 768;           // 0=q 1=k 2=v
    const int h = (colBase % 768) / 64;
    const int d0 = tx * 4;
    float4 bv = *(const float4*)(bias + colBase + d0);
    const float scale = (which == 0) ? 0.125f : 1.0f;
    float* dst = (which == 0) ? g_q : (which == 1) ? g_k : g_v;

#pragma unroll
    for (int i = 0; i < 8; i++) {
        int row = bm * BM + ty * 8 + i;
        int b = row >> 10, n = row & 1023;
        size_t off = ((size_t)(b * HEADS + h) * 1024 + n) * 64 + d0;
        float4 r;
        r.x = (acc[i][0] + bv.x) * scale;
        r.y = (acc[i][1] + bv.y) * scale;
        r.z = (acc[i][2] + bv.z) * scale;
        r.w = (acc[i][3] + bv.w) * scale;
        *(float4*)(dst + off) = r;
    }
}

__global__ __launch_bounds__(256, 2)
void gemm_proj_kernel(const float* __restrict__ W, const float* __restrict__ bias,
                      float* __restrict__ out)
{
    __shared__ float As[BK * LDA_S];
    __shared__ float Bs[BK * LDB_S];

    const int tid = threadIdx.x;
    const int tx = tid & 15;
    const int ty = tid >> 4;
    const int bm = blockIdx.y;
    const int bn = blockIdx.x;

    const float* Ag = g_ao + (size_t)bm * BM * DIMK;
    const float* Wg = W + (size_t)bn * BN * DIMK;

    const int lRow = tid >> 2;
    const int lCol = (tid & 3) * 4;

    float4 aReg0 = *(const float4*)(Ag + (size_t)lRow * DIMK + lCol);
    float4 aReg1 = *(const float4*)(Ag + (size_t)(lRow + 64) * DIMK + lCol);
    float4 wReg  = *(const float4*)(Wg + (size_t)lRow * DIMK + lCol);

    float acc[8][4];
#pragma unroll
    for (int i = 0; i < 8; i++)
#pragma unroll
        for (int j = 0; j < 4; j++) acc[i][j] = 0.f;

    for (int kt = 0; kt < DIMK; kt += BK) {
        __syncthreads();
        As[(lCol + 0) * LDA_S + lRow] = aReg0.x;
        As[(lCol + 1) * LDA_S + lRow] = aReg0.y;
        As[(lCol + 2) * LDA_S + lRow] = aReg0.z;
        As[(lCol + 3) * LDA_S + lRow] = aReg0.w;
        As[(lCol + 0) * LDA_S + lRow + 64] = aReg1.x;
        As[(lCol + 1) * LDA_S + lRow + 64] = aReg1.y;
        As[(lCol + 2) * LDA_S + lRow + 64] = aReg1.z;
        As[(lCol + 3) * LDA_S + lRow + 64] = aReg1.w;
        Bs[(lCol + 0) * LDB_S + lRow] = wReg.x;
        Bs[(lCol + 1) * LDB_S + lRow] = wReg.y;
        Bs[(lCol + 2) * LDB_S + lRow] = wReg.z;
        Bs[(lCol + 3) * LDB_S + lRow] = wReg.w;
        __syncthreads();

        if (kt + BK < DIMK) {
            const int k2 = kt + BK;
            aReg0 = *(const float4*)(Ag + (size_t)lRow * DIMK + k2 + lCol);
            aReg1 = *(const float4*)(Ag + (size_t)(lRow + 64) * DIMK + k2 + lCol);
            wReg  = *(const float4*)(Wg + (size_t)lRow * DIMK + k2 + lCol);
        }

#pragma unroll
        for (int kk = 0; kk < BK; kk++) {
            float4 a0 = *(float4*)&As[kk * LDA_S + ty * 8];
            float4 a1 = *(float4*)&As[kk * LDA_S + ty * 8 + 4];
            float4 b0 = *(float4*)&Bs[kk * LDB_S + tx * 4];
            float a[8] = {a0.x, a0.y, a0.z, a0.w, a1.x, a1.y, a1.z, a1.w};
            float b[4] = {b0.x, b0.y, b0.z, b0.w};
#pragma unroll
            for (int i = 0; i < 8; i++)
#pragma unroll
                for (int j = 0; j < 4; j++)
                    acc[i][j] = fmaf(a[i], b[j], acc[i][j]);
        }
    }

    const int colBase = bn * BN;
    const int d0 = tx * 4;
    float4 bv = *(const float4*)(bias + colBase + d0);
#pragma unroll
    for (int i = 0; i < 8; i++) {
        int row = bm * BM + ty * 8 + i;
        float4 r;
        r.x = acc[i][0] + bv.x;
        r.y = acc[i][1] + bv.y;
        r.z = acc[i][2] + bv.z;
        r.w = acc[i][3] + bv.w;
        *(float4*)(out + (size_t)row * DIMK + colBase + d0) = r;
    }
}

// ---------------- flash attention ----------------
// grid (16, 192): x = 64-row block within seq, y = b*H+h. 256 threads (16x16).
// smem: Qs[d][i] (transposed), KP[d][j] (transposed K, reused as P^T[j][i]), Vs[j][d].
#define LQ 68
#define ATTN_SMEM (3 * 64 * LQ * 4)

__global__ __launch_bounds__(256)
void attn_kernel()
{
    extern __shared__ float sm[];
    float* Qs = sm;
    float* KP = sm + 64 * LQ;
    float* Vs = sm + 2 * 64 * LQ;

    const int tid = threadIdx.x;
    const int tx = tid & 15;
    const int ty = tid >> 4;
    const int bh = blockIdx.y;
    const int r0 = blockIdx.x * 64;

    const float* qb = g_q + ((size_t)bh * 1024 + r0) * 64;
    const float* kb_base = g_k + (size_t)bh * 1024 * 64;
    const float* vb_base = g_v + (size_t)bh * 1024 * 64;

    // load Q transposed: Qs[d][i]
#pragma unroll
    for (int u = 0; u < 4; u++) {
        int row = ty + u * 16;
        float4 t = *(const float4*)(qb + row * 64 + tx * 4);
        Qs[(tx * 4 + 0) * LQ + row] = t.x;
        Qs[(tx * 4 + 1) * LQ + row] = t.y;
        Qs[(tx * 4 + 2) * LQ + row] = t.z;
        Qs[(tx * 4 + 3) * LQ + row] = t.w;
    }

    float m_run[4], l_run[4], o[4][4];
#pragma unroll
    for (int ii = 0; ii < 4; ii++) {
        m_run[ii] = -1e30f;
        l_run[ii] = 0.f;
#pragma unroll
        for (int dd = 0; dd < 4; dd++) o[ii][dd] = 0.f;
    }

    for (int kb = 0; kb < 16; kb++) {
        const float* kp = kb_base + (size_t)kb * 64 * 64;
        const float* vp = vb_base + (size_t)kb * 64 * 64;
        __syncthreads();   // prior PV done; KP/Vs reusable (also orders first-iter Q load)
#pragma unroll
        for (int u = 0; u < 4; u++) {
            int row = ty + u * 16;
            float4 kk4 = *(const float4*)(kp + row * 64 + tx * 4);
            KP[(tx * 4 + 0) * LQ + row] = kk4.x;
            KP[(tx * 4 + 1) * LQ + row] = kk4.y;
            KP[(tx * 4 + 2) * LQ + row] = kk4.z;
            KP[(tx * 4 + 3) * LQ + row] = kk4.w;
            float4 vv4 = *(const float4*)(vp + row * 64 + tx * 4);
            *(float4*)&Vs[row * LQ + tx * 4] = vv4;
        }
        __syncthreads();

        // S tile: s[ii][jj] = sum_d Q[i][d]*K[j][d]  (Q pre-scaled)
        float s[4][4];
#pragma unroll
        for (int ii = 0; ii < 4; ii++)
#pragma unroll
            for (int jj = 0; jj < 4; jj++) s[ii][jj] = 0.f;
#pragma unroll 16
        for (int d = 0; d < 64; d++) {
            float4 qf = *(float4*)&Qs[d * LQ + ty * 4];
            float4 kf = *(float4*)&KP[d * LQ + tx * 4];
            float qa[4] = {qf.x, qf.y, qf.z, qf.w};
            float ka[4] = {kf.x, kf.y, kf.z, kf.w};
#pragma unroll
            for (int ii = 0; ii < 4; ii++)
#pragma unroll
                for (int jj = 0; jj < 4; jj++)
                    s[ii][jj] = fmaf(qa[ii], ka[jj], s[ii][jj]);
        }

        // online softmax (row i owned by 16 lanes sharing ty; width-16 xor shuffles)
#pragma unroll
        for (int ii = 0; ii < 4; ii++) {
            float mx = fmaxf(fmaxf(s[ii][0], s[ii][1]), fmaxf(s[ii][2], s[ii][3]));
#pragma unroll
            for (int off = 8; off > 0; off >>= 1)
                mx = fmaxf(mx, __shfl_xor_sync(0xffffffffu, mx, off, 16));
            float mnew = fmaxf(m_run[ii], mx);
            float sum = 0.f;
#pragma unroll
            for (int jj = 0; jj < 4; jj++) {
                s[ii][jj] = __expf(s[ii][jj] - mnew);
                sum += s[ii][jj];
            }
#pragma unroll
            for (int off = 8; off > 0; off >>= 1)
                sum += __shfl_xor_sync(0xffffffffu, sum, off, 16);
            float alpha = __expf(m_run[ii] - mnew);
            l_run[ii] = l_run[ii] * alpha + sum;
            m_run[ii] = mnew;
#pragma unroll
            for (int dd = 0; dd < 4; dd++) o[ii][dd] *= alpha;
        }

        __syncthreads();   // all K reads done; reuse KP for P^T
#pragma unroll
        for (int jj = 0; jj < 4; jj++) {
            float4 pv = make_float4(s[0][jj], s[1][jj], s[2][jj], s[3][jj]);
            *(float4*)&KP[(tx * 4 + jj) * LQ + ty * 4] = pv;
        }
        __syncthreads();

        // O += P @ V
#pragma unroll 16
        for (int j = 0; j < 64; j++) {
            float4 pf = *(float4*)&KP[j * LQ + ty * 4];
            float4 vf = *(float4*)&Vs[j * LQ + tx * 4];
            float pa[4] = {pf.x, pf.y, pf.z, pf.w};
            float va[4] = {vf.x, vf.y, vf.z, vf.w};
#pragma unroll
            for (int ii = 0; ii < 4; ii++)
#pragma unroll
                for (int dd = 0; dd < 4; dd++)
                    o[ii][dd] = fmaf(pa[ii], va[dd], o[ii][dd]);
        }
    }

    // epilogue -> g_ao [B*N][768] (heads interleaved back to C layout)
    const int b = bh / HEADS;
    const int h = bh % HEADS;
#pragma unroll
    for (int ii = 0; ii < 4; ii++) {
        float inv = 1.0f / l_run[ii];
        int n = r0 + ty * 4 + ii;
        float4 r = make_float4(o[ii][0] * inv, o[ii][1] * inv, o[ii][2] * inv, o[ii][3] * inv);
        *(float4*)(g_ao + ((size_t)(b * 1024 + n)) * DIMK + h * 64 + tx * 4) = r;
    }
}

// ---------------- launch ----------------
extern "C" void kernel_launch(void* const* d_in, const int* in_sizes, int n_in,
                              void* d_out, int out_size)
{
    const float* x      = (const float*)d_in[0];
    const float* qkv_w  = (const float*)d_in[1];
    const float* qkv_b  = (const float*)d_in[2];
    // d_in[3] = qkv_B (unused feedback-alignment buffer)
    const float* proj_w = (const float*)d_in[4];
    const float* proj_b = (const float*)d_in[5];
    // d_in[6] = proj_B (unused)
    float* out = (float*)d_out;

    cudaFuncSetAttribute(attn_kernel, cudaFuncAttributeMaxDynamicSharedMemorySize, ATTN_SMEM);

    gemm_qkv_kernel<<<dim3(36, 128), 256>>>(x, qkv_w, qkv_b);
    attn_kernel<<<dim3(16, 192), 256, ATTN_SMEM>>>();
    gemm_proj_kernel<<<dim3(12, 128), 256>>>(proj_w, proj_b, out);
}

// round 4
// speedup vs baseline: 3.3496x; 3.3496x over previous
#include <cuda_runtime.h>
#include <cstdint>
#include <math.h>

// Shapes (fixed): B=16, N=1024, C=768, H=12, hd=64
#define DIMK 768
#define HEADS 12

// ---------------- scratch (no cudaMalloc allowed) ----------------
__device__ __align__(16) float g_q[12582912];   // [B*H][1024][64], pre-scaled by 0.125
__device__ __align__(16) float g_k[12582912];   // [B*H][1024][64]
__device__ __align__(16) float g_v[12582912];   // [B*H][1024][64]
__device__ __align__(16) float g_ao[12582912];  // [B*N][768] attention output

// ---------------- PTX helpers (sm_100-plain compatible: mma.sync/ldmatrix/cp.async) ----
__device__ __forceinline__ uint32_t smem_u32(const void* p) {
    uint32_t a;
    asm("{ .reg .u64 t; cvta.to.shared.u64 t, %1; cvt.u32.u64 %0, t; }" : "=r"(a) : "l"(p));
    return a;
}
__device__ __forceinline__ void cp16(uint32_t dst, const void* src) {
    asm volatile("cp.async.cg.shared.global [%0], [%1], 16;" :: "r"(dst), "l"(src));
}
#define CP_COMMIT() asm volatile("cp.async.commit_group;" ::: "memory")
#define CP_WAIT1()  asm volatile("cp.async.wait_group 1;" ::: "memory")

__device__ __forceinline__ void ldsm4(uint32_t& r0, uint32_t& r1, uint32_t& r2, uint32_t& r3,
                                      uint32_t addr) {
    asm volatile("ldmatrix.sync.aligned.m8n8.x4.shared.b16 {%0,%1,%2,%3}, [%4];"
                 : "=r"(r0), "=r"(r1), "=r"(r2), "=r"(r3) : "r"(addr));
}
__device__ __forceinline__ void cvt_tf32(uint32_t& x) {
    asm volatile("cvt.rna.tf32.f32 %0, %0;" : "+r"(x));
}
__device__ __forceinline__ uint32_t f2tf(float f) {
    uint32_t r;
    asm volatile("cvt.rna.tf32.f32 %0, %1;" : "=r"(r) : "f"(f));
    return r;
}
__device__ __forceinline__ void mma_tf32(float c[4], const uint32_t a[4],
                                         uint32_t b0, uint32_t b1) {
    asm volatile("mma.sync.aligned.m16n8k8.row.col.f32.tf32.tf32.f32 "
                 "{%0,%1,%2,%3}, {%4,%5,%6,%7}, {%8,%9}, {%0,%1,%2,%3};"
                 : "+f"(c[0]), "+f"(c[1]), "+f"(c[2]), "+f"(c[3])
                 : "r"(a[0]), "r"(a[1]), "r"(a[2]), "r"(a[3]), "r"(b0), "r"(b1));
}

// ======================= GEMM (mma.sync tf32) =======================
// C[m][n] = sum_k A[m][k] * W[n][k]. BM=128 BN=128 BK=32, 256 thr (8 warps 4x2),
// warp tile 32x64. Smem: 16B atoms, atom (row,k4) at row*128 + ((k4^(row&7))<<4).
#define GSTG_BYTES 32768          // A 16KB + B 16KB per stage
#define GSM_TOTAL (3 * GSTG_BYTES)

__device__ __forceinline__ void g_load_stage(uint32_t sbase, const float* __restrict__ Ag,
                                             const float* __restrict__ Bg, int kt, int tid)
{
    const int kof = kt * 32;
#pragma unroll
    for (int i = 0; i < 4; i++) {
        int a = i * 256 + tid;
        int row = a >> 3, k4 = a & 7;
        cp16(sbase + row * 128 + (((k4 ^ row) & 7) << 4),
             Ag + (size_t)row * DIMK + kof + k4 * 4);
    }
#pragma unroll
    for (int i = 0; i < 4; i++) {
        int a = i * 256 + tid;
        int row = a >> 3, k4 = a & 7;
        cp16(sbase + 16384 + row * 128 + (((k4 ^ row) & 7) << 4),
             Bg + (size_t)row * DIMK + kof + k4 * 4);
    }
}

__device__ __forceinline__ void g_compute(uint32_t abase, uint32_t bbase,
                                          float acc[2][8][4], int lane, int wm, int wn)
{
    const int l15 = lane & 15;
    const int lhi = lane >> 4;            // k-half select for A
    const int brow_in = (lane & 7) + ((lane >> 4) << 3);
    const int bk_sel = (lane >> 3) & 1;
#pragma unroll
    for (int ks = 0; ks < 4; ks++) {
        uint32_t ar[2][4];
#pragma unroll
        for (int i = 0; i < 2; i++) {
            int row = wm * 32 + i * 16 + l15;
            int k4 = ks * 2 + lhi;
            ldsm4(ar[i][0], ar[i][1], ar[i][2], ar[i][3],
                  abase + row * 128 + (((k4 ^ row) & 7) << 4));
            cvt_tf32(ar[i][0]); cvt_tf32(ar[i][1]); cvt_tf32(ar[i][2]); cvt_tf32(ar[i][3]);
        }
        uint32_t br[8][2];
#pragma unroll
        for (int p = 0; p < 4; p++) {
            int row = wn * 64 + p * 16 + brow_in;
            int k4 = ks * 2 + bk_sel;
            uint32_t r0, r1, r2, r3;
            ldsm4(r0, r1, r2, r3, bbase + row * 128 + (((k4 ^ row) & 7) << 4));
            cvt_tf32(r0); cvt_tf32(r1); cvt_tf32(r2); cvt_tf32(r3);
            br[2 * p][0] = r0; br[2 * p][1] = r1;
            br[2 * p + 1][0] = r2; br[2 * p + 1][1] = r3;
        }
#pragma unroll
        for (int i = 0; i < 2; i++)
#pragma unroll
            for (int j = 0; j < 8; j++)
                mma_tf32(acc[i][j], ar[i], br[j][0], br[j][1]);
    }
}

#define GEMM_MAIN(Ag, Bg)                                                        \
    extern __shared__ char smem[];                                               \
    const uint32_t sb = smem_u32(smem);                                          \
    const int tid = threadIdx.x, lane = tid & 31, wid = tid >> 5;                \
    const int wm = wid & 3, wn = wid >> 2;                                       \
    float acc[2][8][4];                                                          \
    _Pragma("unroll") for (int i = 0; i < 2; i++)                                \
        _Pragma("unroll") for (int j = 0; j < 8; j++)                            \
            _Pragma("unroll") for (int q = 0; q < 4; q++) acc[i][j][q] = 0.f;    \
    g_load_stage(sb, Ag, Bg, 0, tid); CP_COMMIT();                               \
    g_load_stage(sb + GSTG_BYTES, Ag, Bg, 1, tid); CP_COMMIT();                  \
    for (int kt = 0; kt < 24; kt++) {                                            \
        CP_WAIT1();                                                              \
        __syncthreads();                                                         \
        if (kt + 2 < 24)                                                         \
            g_load_stage(sb + ((kt + 2) % 3) * GSTG_BYTES, Ag, Bg, kt + 2, tid); \
        CP_COMMIT();                                                             \
        uint32_t st = sb + (kt % 3) * GSTG_BYTES;                                \
        g_compute(st, st + 16384, acc, lane, wm, wn);                            \
    }

__global__ __launch_bounds__(256, 2)
void gemm_qkv_mm(const float* __restrict__ X, const float* __restrict__ W,
                 const float* __restrict__ bias)
{
    const int m0 = blockIdx.y * 128;
    const int n0 = blockIdx.x * 128;
    GEMM_MAIN(X + (size_t)m0 * DIMK, W + (size_t)n0 * DIMK)

    // epilogue: scatter to g_q/g_k/g_v [bh][n][64]; warp's 64-col slice = one head chunk
    const int g = lane >> 2, t4 = lane & 3;
    const int cb = n0 + wn * 64;
    const int which = cb / 768;
    const int h = (cb % 768) / 64;
    const float scale = (which == 0) ? 0.125f : 1.0f;
    float* dst = (which == 0) ? g_q : (which == 1) ? g_k : g_v;
#pragma unroll
    for (int i = 0; i < 2; i++) {
#pragma unroll
        for (int j = 0; j < 8; j++) {
            const int col = j * 8 + t4 * 2;
            const float2 bv = *(const float2*)(bias + cb + col);
            int m = m0 + wm * 32 + i * 16 + g;
            int b = m >> 10, n = m & 1023;
            float2 v0 = make_float2((acc[i][j][0] + bv.x) * scale,
                                    (acc[i][j][1] + bv.y) * scale);
            *(float2*)(dst + ((size_t)(b * HEADS + h) * 1024 + n) * 64 + col) = v0;
            m += 8; b = m >> 10; n = m & 1023;
            float2 v1 = make_float2((acc[i][j][2] + bv.x) * scale,
                                    (acc[i][j][3] + bv.y) * scale);
            *(float2*)(dst + ((size_t)(b * HEADS + h) * 1024 + n) * 64 + col) = v1;
        }
    }
}

__global__ __launch_bounds__(256, 2)
void gemm_proj_mm(const float* __restrict__ W, const float* __restrict__ bias,
                  float* __restrict__ out)
{
    const int m0 = blockIdx.y * 128;
    const int n0 = blockIdx.x * 128;
    GEMM_MAIN(g_ao + (size_t)m0 * DIMK, W + (size_t)n0 * DIMK)

    const int g = lane >> 2, t4 = lane & 3;
#pragma unroll
    for (int i = 0; i < 2; i++) {
#pragma unroll
        for (int j = 0; j < 8; j++) {
            const int col = n0 + wn * 64 + j * 8 + t4 * 2;
            const float2 bv = *(const float2*)(bias + col);
            const int m = m0 + wm * 32 + i * 16 + g;
            *(float2*)(out + (size_t)m * DIMK + col) =
                make_float2(acc[i][j][0] + bv.x, acc[i][j][1] + bv.y);
            *(float2*)(out + (size_t)(m + 8) * DIMK + col) =
                make_float2(acc[i][j][2] + bv.x, acc[i][j][3] + bv.y);
        }
    }
}

// ======================= Flash attention (mma.sync tf32) =======================
// 128 thr (4 warps), Br=64 (16 rows/warp), Bc=64, d=64.
// Qs/Ks: 64 rows x 64 floats, 16B-atom swizzled (16 atoms/row):
//   addr = row*256 + (((k4 & 8) | ((k4 ^ row) & 7)) << 4)
// Vs: [key][72] plain (pad->conflict-free B-frag LDS). Ps: uint tf32 [64][68].
#define AQ_OFF 0
#define AK_OFF 16384             // 2 x 16384
#define AV_OFF 49152             // 2 x 18432
#define AP_OFF 86016             // 64*68*4 = 17408
#define ASM_TOTAL 103424

__device__ __forceinline__ uint32_t qk_addr(uint32_t base, int row, int k4) {
    return base + row * 256 + ((((k4 & 8) | ((k4 ^ row) & 7))) << 4);
}

__device__ __forceinline__ void a_load_qk(uint32_t sbase, const float* __restrict__ src, int tid) {
#pragma unroll
    for (int i = 0; i < 8; i++) {
        int a = i * 128 + tid;
        int row = a >> 4, k4 = a & 15;
        cp16(qk_addr(sbase, row, k4), src + (size_t)row * 64 + k4 * 4);
    }
}
__device__ __forceinline__ void a_load_v(uint32_t sbase, const float* __restrict__ src, int tid) {
#pragma unroll
    for (int i = 0; i < 8; i++) {
        int a = i * 128 + tid;
        int row = a >> 4, c4 = a & 15;
        cp16(sbase + row * 288 + c4 * 16, src + (size_t)row * 64 + c4 * 4);
    }
}

__global__ __launch_bounds__(128, 2)
void attn_mm()
{
    extern __shared__ char smem[];
    const uint32_t sb = smem_u32(smem);
    float* Vsf = (float*)(smem + AV_OFF);
    uint32_t* Ps = (uint32_t*)(smem + AP_OFF);

    const int tid = threadIdx.x, lane = tid & 31, w = tid >> 5;
    const int g = lane >> 2, t4 = lane & 3;
    const int bh = blockIdx.y;
    const int r0 = blockIdx.x * 64;

    const float* qp = g_q + ((size_t)bh * 1024 + r0) * 64;
    const float* kbase = g_k + (size_t)bh * 1024 * 64;
    const float* vbase = g_v + (size_t)bh * 1024 * 64;

    // prologue: Q + chunk0 K/V, one group
    a_load_qk(sb + AQ_OFF, qp, tid);
    a_load_qk(sb + AK_OFF, kbase, tid);
    a_load_v(sb + AV_OFF, vbase, tid);
    CP_COMMIT();

    float o[8][4];
    float m0v = -1e30f, m1v = -1e30f, l0 = 0.f, l1 = 0.f;
#pragma unroll
    for (int j = 0; j < 8; j++)
#pragma unroll
        for (int q = 0; q < 4; q++) o[j][q] = 0.f;

    const int a_l15 = lane & 15, a_lhi = lane >> 4;
    const int b_row_in = (lane & 7) + ((lane >> 4) << 3);
    const int b_k_sel = (lane >> 3) & 1;

    for (int c = 0; c < 16; c++) {
        __syncthreads();                       // prior chunk fully consumed
        if (c + 1 < 16) {
            a_load_qk(sb + AK_OFF + ((c + 1) & 1) * 16384, kbase + (size_t)(c + 1) * 4096, tid);
            a_load_v(sb + AV_OFF + ((c + 1) & 1) * 18432, vbase + (size_t)(c + 1) * 4096, tid);
        }
        CP_COMMIT();
        CP_WAIT1();                            // chunk c ready
        __syncthreads();

        const uint32_t kb = sb + AK_OFF + (c & 1) * 16384;
        const float* vb = Vsf + (c & 1) * 4608;     // 18432 bytes / 4

        // ---- S = Q @ K^T (Q pre-scaled) ----
        float s[8][4];
#pragma unroll
        for (int j = 0; j < 8; j++)
#pragma unroll
            for (int q = 0; q < 4; q++) s[j][q] = 0.f;
#pragma unroll
        for (int ks = 0; ks < 8; ks++) {
            uint32_t ar[4];
            {
                int row = w * 16 + a_l15;
                int k4 = ks * 2 + a_lhi;
                ldsm4(ar[0], ar[1], ar[2], ar[3], qk_addr(sb + AQ_OFF, row, k4));
                cvt_tf32(ar[0]); cvt_tf32(ar[1]); cvt_tf32(ar[2]); cvt_tf32(ar[3]);
            }
#pragma unroll
            for (int p = 0; p < 4; p++) {
                int row = p * 16 + b_row_in;
                int k4 = ks * 2 + b_k_sel;
                uint32_t r0b, r1b, r2b, r3b;
                ldsm4(r0b, r1b, r2b, r3b, qk_addr(kb, row, k4));
                cvt_tf32(r0b); cvt_tf32(r1b); cvt_tf32(r2b); cvt_tf32(r3b);
                mma_tf32(s[2 * p], ar, r0b, r1b);
                mma_tf32(s[2 * p + 1], ar, r2b, r3b);
            }
        }

        // ---- online softmax (rows g and g+8 of this warp's 16) ----
        float mx0 = -1e30f, mx1 = -1e30f;
#pragma unroll
        for (int j = 0; j < 8; j++) {
            mx0 = fmaxf(mx0, fmaxf(s[j][0], s[j][1]));
            mx1 = fmaxf(mx1, fmaxf(s[j][2], s[j][3]));
        }
        mx0 = fmaxf(mx0, __shfl_xor_sync(0xffffffffu, mx0, 1));
        mx0 = fmaxf(mx0, __shfl_xor_sync(0xffffffffu, mx0, 2));
        mx1 = fmaxf(mx1, __shfl_xor_sync(0xffffffffu, mx1, 1));
        mx1 = fmaxf(mx1, __shfl_xor_sync(0xffffffffu, mx1, 2));
        const float mn0 = fmaxf(m0v, mx0), mn1 = fmaxf(m1v, mx1);
        float sum0 = 0.f, sum1 = 0.f;
#pragma unroll
        for (int j = 0; j < 8; j++) {
            s[j][0] = __expf(s[j][0] - mn0);
            s[j][1] = __expf(s[j][1] - mn0);
            s[j][2] = __expf(s[j][2] - mn1);
            s[j][3] = __expf(s[j][3] - mn1);
            sum0 += s[j][0] + s[j][1];
            sum1 += s[j][2] + s[j][3];
        }
        sum0 += __shfl_xor_sync(0xffffffffu, sum0, 1);
        sum0 += __shfl_xor_sync(0xffffffffu, sum0, 2);
        sum1 += __shfl_xor_sync(0xffffffffu, sum1, 1);
        sum1 += __shfl_xor_sync(0xffffffffu, sum1, 2);
        const float al0 = __expf(m0v - mn0), al1 = __expf(m1v - mn1);
        l0 = l0 * al0 + sum0; l1 = l1 * al1 + sum1;
        m0v = mn0; m1v = mn1;
#pragma unroll
        for (int j = 0; j < 8; j++) {
            o[j][0] *= al0; o[j][1] *= al0;
            o[j][2] *= al1; o[j][3] *= al1;
        }

        // ---- P -> smem (tf32 bits); warp-private rows -> syncwarp only ----
        const int ra = w * 16 + g, rb = ra + 8;
#pragma unroll
        for (int j = 0; j < 8; j++) {
            const int col = j * 8 + t4 * 2;
            *(uint2*)&Ps[ra * 68 + col] = make_uint2(f2tf(s[j][0]), f2tf(s[j][1]));
            *(uint2*)&Ps[rb * 68 + col] = make_uint2(f2tf(s[j][2]), f2tf(s[j][3]));
        }
        __syncwarp();

        // ---- O += P @ V ----
#pragma unroll
        for (int kk = 0; kk < 8; kk++) {
            uint32_t pa[4];
            pa[0] = Ps[ra * 68 + kk * 8 + t4];
            pa[1] = Ps[rb * 68 + kk * 8 + t4];
            pa[2] = Ps[ra * 68 + kk * 8 + t4 + 4];
            pa[3] = Ps[rb * 68 + kk * 8 + t4 + 4];
#pragma unroll
            for (int j = 0; j < 8; j++) {
                uint32_t v0 = f2tf(vb[(kk * 8 + t4) * 72 + j * 8 + g]);
                uint32_t v1 = f2tf(vb[(kk * 8 + t4 + 4) * 72 + j * 8 + g]);
                mma_tf32(o[j], pa, v0, v1);
            }
        }
    }

    // epilogue -> g_ao [B*N][768]
    const int b = bh / HEADS, h = bh % HEADS;
    const float i0 = 1.0f / l0, i1 = 1.0f / l1;
    const int na = r0 + w * 16 + g;
#pragma unroll
    for (int j = 0; j < 8; j++) {
        const int col = h * 64 + j * 8 + t4 * 2;
        *(float2*)(g_ao + ((size_t)(b * 1024 + na)) * DIMK + col) =
            make_float2(o[j][0] * i0, o[j][1] * i0);
        *(float2*)(g_ao + ((size_t)(b * 1024 + na + 8)) * DIMK + col) =
            make_float2(o[j][2] * i1, o[j][3] * i1);
    }
}

// ---------------- launch ----------------
extern "C" void kernel_launch(void* const* d_in, const int* in_sizes, int n_in,
                              void* d_out, int out_size)
{
    const float* x      = (const float*)d_in[0];
    const float* qkv_w  = (const float*)d_in[1];
    const float* qkv_b  = (const float*)d_in[2];
    // d_in[3] = qkv_B (unused feedback-alignment buffer)
    const float* proj_w = (const float*)d_in[4];
    const float* proj_b = (const float*)d_in[5];
    // d_in[6] = proj_B (unused)
    float* out = (float*)d_out;

    cudaFuncSetAttribute(gemm_qkv_mm, cudaFuncAttributeMaxDynamicSharedMemorySize, GSM_TOTAL);
    cudaFuncSetAttribute(gemm_proj_mm, cudaFuncAttributeMaxDynamicSharedMemorySize, GSM_TOTAL);
    cudaFuncSetAttribute(attn_mm, cudaFuncAttributeMaxDynamicSharedMemorySize, ASM_TOTAL);

    gemm_qkv_mm<<<dim3(18, 128), 256, GSM_TOTAL>>>(x, qkv_w, qkv_b);
    attn_mm<<<dim3(16, 192), 128, ASM_TOTAL>>>();
    gemm_proj_mm<<<dim3(6, 128), 256, GSM_TOTAL>>>(proj_w, proj_b, out);
}

// round 6
// speedup vs baseline: 4.0517x; 1.2096x over previous
#include <cuda_runtime.h>
#include <cstdint>
#include <math.h>

// Shapes (fixed): B=16, N=1024, C=768, H=12, hd=64
#define DIMK 768
#define HEADS 12

// ---------------- scratch (no cudaMalloc allowed) ----------------
__device__ __align__(16) float g_q[12582912];   // [B*H][1024][64], tf32-rounded, pre-scaled
__device__ __align__(16) float g_k[12582912];   // [B*H][1024][64], tf32-rounded
__device__ __align__(16) float g_v[12582912];   // [B*H][64][1024]  V^T, tf32-rounded
__device__ __align__(16) float g_ao[12582912];  // [B*N][768] attn out, tf32-rounded
__device__ __align__(16) float g_xr[12582912];  // X pre-rounded to tf32
__device__ __align__(16) float g_wq[1769472];   // qkv_w pre-rounded
__device__ __align__(16) float g_wp[589824];    // proj_w pre-rounded

// ---------------- PTX helpers ----------------
__device__ __forceinline__ uint32_t smem_u32(const void* p) {
    uint32_t a;
    asm("{ .reg .u64 t; cvta.to.shared.u64 t, %1; cvt.u32.u64 %0, t; }" : "=r"(a) : "l"(p));
    return a;
}
__device__ __forceinline__ void cp16(uint32_t dst, const void* src) {
    asm volatile("cp.async.cg.shared.global [%0], [%1], 16;" :: "r"(dst), "l"(src));
}
#define CP_COMMIT() asm volatile("cp.async.commit_group;" ::: "memory")
#define CP_WAIT1()  asm volatile("cp.async.wait_group 1;" ::: "memory")

__device__ __forceinline__ void ldsm4(uint32_t& r0, uint32_t& r1, uint32_t& r2, uint32_t& r3,
                                      uint32_t addr) {
    asm volatile("ldmatrix.sync.aligned.m8n8.x4.shared.b16 {%0,%1,%2,%3}, [%4];"
                 : "=r"(r0), "=r"(r1), "=r"(r2), "=r"(r3) : "r"(addr));
}
__device__ __forceinline__ uint32_t f2tf(float f) {
    uint32_t r;
    asm volatile("cvt.rna.tf32.f32 %0, %1;" : "=r"(r) : "f"(f));
    return r;
}
__device__ __forceinline__ float rtf(float f) { return __uint_as_float(f2tf(f)); }
__device__ __forceinline__ void mma_tf32(float c[4], const uint32_t a[4],
                                         uint32_t b0, uint32_t b1) {
    asm volatile("mma.sync.aligned.m16n8k8.row.col.f32.tf32.tf32.f32 "
                 "{%0,%1,%2,%3}, {%4,%5,%6,%7}, {%8,%9}, {%0,%1,%2,%3};"
                 : "+f"(c[0]), "+f"(c[1]), "+f"(c[2]), "+f"(c[3])
                 : "r"(a[0]), "r"(a[1]), "r"(a[2]), "r"(a[3]), "r"(b0), "r"(b1));
}

// ---------------- pre-round to tf32 ----------------
__global__ void preround_k(const float4* __restrict__ s, float4* __restrict__ d, int n4)
{
    int i = blockIdx.x * blockDim.x + threadIdx.x;
    if (i < n4) {
        float4 v = s[i];
        v.x = rtf(v.x); v.y = rtf(v.y); v.z = rtf(v.z); v.w = rtf(v.w);
        d[i] = v;
    }
}

// ======================= GEMM (mma.sync tf32, operands pre-rounded) =======================
// C[m][n] = sum_k A[m][k] * W[n][k]. BM=128 BN=128 BK=32, 256 thr (8 warps 4x2),
// warp tile 32x64. Smem: 16B atoms, atom (row,k4) at row*128 + ((k4^row&7)<<4).
#define GSTG_BYTES 32768
#define GSM_TOTAL (3 * GSTG_BYTES)

__device__ __forceinline__ void g_load_stage(uint32_t sbase, const float* __restrict__ Ag,
                                             const float* __restrict__ Bg, int kt, int tid)
{
    const int kof = kt * 32;
#pragma unroll
    for (int i = 0; i < 4; i++) {
        int a = i * 256 + tid;
        int row = a >> 3, k4 = a & 7;
        cp16(sbase + row * 128 + (((k4 ^ row) & 7) << 4),
             Ag + (size_t)row * DIMK + kof + k4 * 4);
    }
#pragma unroll
    for (int i = 0; i < 4; i++) {
        int a = i * 256 + tid;
        int row = a >> 3, k4 = a & 7;
        cp16(sbase + 16384 + row * 128 + (((k4 ^ row) & 7) << 4),
             Bg + (size_t)row * DIMK + kof + k4 * 4);
    }
}

__device__ __forceinline__ void g_compute(uint32_t abase, uint32_t bbase,
                                          float acc[2][8][4], int lane, int wm, int wn)
{
    const int l15 = lane & 15;
    const int lhi = lane >> 4;
    const int brow_in = (lane & 7) + ((lane >> 4) << 3);
    const int bk_sel = (lane >> 3) & 1;
#pragma unroll
    for (int ks = 0; ks < 4; ks++) {
        uint32_t ar[2][4];
#pragma unroll
        for (int i = 0; i < 2; i++) {
            int row = wm * 32 + i * 16 + l15;
            int k4 = ks * 2 + lhi;
            ldsm4(ar[i][0], ar[i][1], ar[i][2], ar[i][3],
                  abase + row * 128 + (((k4 ^ row) & 7) << 4));
        }
        uint32_t br[8][2];
#pragma unroll
        for (int p = 0; p < 4; p++) {
            int row = wn * 64 + p * 16 + brow_in;
            int k4 = ks * 2 + bk_sel;
            uint32_t r0, r1, r2, r3;
            ldsm4(r0, r1, r2, r3, bbase + row * 128 + (((k4 ^ row) & 7) << 4));
            br[2 * p][0] = r0; br[2 * p][1] = r1;
            br[2 * p + 1][0] = r2; br[2 * p + 1][1] = r3;
        }
#pragma unroll
        for (int i = 0; i < 2; i++)
#pragma unroll
            for (int j = 0; j < 8; j++)
                mma_tf32(acc[i][j], ar[i], br[j][0], br[j][1]);
    }
}

#define GEMM_MAIN(Ag, Bg)                                                        \
    extern __shared__ char smem[];                                               \
    const uint32_t sb = smem_u32(smem);                                          \
    const int tid = threadIdx.x, lane = tid & 31, wid = tid >> 5;                \
    const int wm = wid & 3, wn = wid >> 2;                                       \
    float acc[2][8][4];                                                          \
    _Pragma("unroll") for (int i = 0; i < 2; i++)                                \
        _Pragma("unroll") for (int j = 0; j < 8; j++)                            \
            _Pragma("unroll") for (int q = 0; q < 4; q++) acc[i][j][q] = 0.f;    \
    g_load_stage(sb, Ag, Bg, 0, tid); CP_COMMIT();                               \
    g_load_stage(sb + GSTG_BYTES, Ag, Bg, 1, tid); CP_COMMIT();                  \
    for (int kt = 0; kt < 24; kt++) {                                            \
        CP_WAIT1();                                                              \
        __syncthreads();                                                         \
        if (kt + 2 < 24)                                                         \
            g_load_stage(sb + ((kt + 2) % 3) * GSTG_BYTES, Ag, Bg, kt + 2, tid); \
        CP_COMMIT();                                                             \
        uint32_t st = sb + (kt % 3) * GSTG_BYTES;                                \
        g_compute(st, st + 16384, acc, lane, wm, wn);                            \
    }

__global__ __launch_bounds__(256, 2)
void gemm_qkv_mm(const float* __restrict__ bias)
{
    const int m0 = blockIdx.y * 128;
    const int n0 = blockIdx.x * 128;
    GEMM_MAIN(g_xr + (size_t)m0 * DIMK, g_wq + (size_t)n0 * DIMK)

    // epilogue: scatter to g_q/g_k (row-major) or g_v (transposed); tf32-rounded
    const int g = lane >> 2, t4 = lane & 3;
    const int cb = n0 + wn * 64;
    const int which = cb / 768;            // 0=q 1=k 2=v
    const int h = (cb % 768) / 64;
    if (which < 2) {
        const float scale = (which == 0) ? 0.125f : 1.0f;
        float* dst = (which == 0) ? g_q : g_k;
#pragma unroll
        for (int i = 0; i < 2; i++) {
#pragma unroll
            for (int j = 0; j < 8; j++) {
                const int col = j * 8 + t4 * 2;
                const float2 bv = *(const float2*)(bias + cb + col);
                int m = m0 + wm * 32 + i * 16 + g;
                int b = m >> 10, n = m & 1023;
                float2 v0 = make_float2(rtf((acc[i][j][0] + bv.x) * scale),
                                        rtf((acc[i][j][1] + bv.y) * scale));
                *(float2*)(dst + ((size_t)(b * HEADS + h) * 1024 + n) * 64 + col) = v0;
                m += 8; b = m >> 10; n = m & 1023;
                float2 v1 = make_float2(rtf((acc[i][j][2] + bv.x) * scale),
                                        rtf((acc[i][j][3] + bv.y) * scale));
                *(float2*)(dst + ((size_t)(b * HEADS + h) * 1024 + n) * 64 + col) = v1;
            }
        }
    } else {
        // V^T: g_v[bh][d][1024]
#pragma unroll
        for (int i = 0; i < 2; i++) {
#pragma unroll
            for (int j = 0; j < 8; j++) {
                const int col = j * 8 + t4 * 2;
                const float2 bv = *(const float2*)(bias + cb + col);
                int m = m0 + wm * 32 + i * 16 + g;
                int b = m >> 10, n = m & 1023;
                size_t base = (size_t)(b * HEADS + h) * 65536;
                g_v[base + (size_t)(col + 0) * 1024 + n] = rtf(acc[i][j][0] + bv.x);
                g_v[base + (size_t)(col + 1) * 1024 + n] = rtf(acc[i][j][1] + bv.y);
                m += 8; b = m >> 10; n = m & 1023;
                base = (size_t)(b * HEADS + h) * 65536;
                g_v[base + (size_t)(col + 0) * 1024 + n] = rtf(acc[i][j][2] + bv.x);
                g_v[base + (size_t)(col + 1) * 1024 + n] = rtf(acc[i][j][3] + bv.y);
            }
        }
    }
}

__global__ __launch_bounds__(256, 2)
void gemm_proj_mm(const float* __restrict__ bias, float* __restrict__ out)
{
    const int m0 = blockIdx.y * 128;
    const int n0 = blockIdx.x * 128;
    GEMM_MAIN(g_ao + (size_t)m0 * DIMK, g_wp + (size_t)n0 * DIMK)

    const int g = lane >> 2, t4 = lane & 3;
#pragma unroll
    for (int i = 0; i < 2; i++) {
#pragma unroll
        for (int j = 0; j < 8; j++) {
            const int col = n0 + wn * 64 + j * 8 + t4 * 2;
            const float2 bv = *(const float2*)(bias + col);
            const int m = m0 + wm * 32 + i * 16 + g;
            *(float2*)(out + (size_t)m * DIMK + col) =
                make_float2(acc[i][j][0] + bv.x, acc[i][j][1] + bv.y);
            *(float2*)(out + (size_t)(m + 8) * DIMK + col) =
                make_float2(acc[i][j][2] + bv.x, acc[i][j][3] + bv.y);
        }
    }
}

// ======================= Flash attention (mma.sync tf32) =======================
// 256 thr (8 warps), Br=128 (16 rows/warp), Bc=64, d=64. All operands pre-rounded tf32.
// Q: 128 rows x 256B swizzled. K: [key][64] rows. V^T: [d][key] rows (same layout).
// P transposed accum->A-frag via register shuffles (no smem).
#define AQ_OFF 0                 // 32768
#define AK_OFF 32768             // 2 x 16384
#define AV_OFF 65536             // 2 x 16384
#define ASM_TOTAL 98304

__device__ __forceinline__ uint32_t qk_addr(uint32_t base, int row, int k4) {
    return base + row * 256 + ((((k4 & 8) | ((k4 ^ row) & 7))) << 4);
}

__global__ __launch_bounds__(256, 2)
void attn_mm()
{
    extern __shared__ char smem[];
    const uint32_t sb = smem_u32(smem);

    const int tid = threadIdx.x, lane = tid & 31, w = tid >> 5;
    const int g = lane >> 2, t4 = lane & 3;
    const int bh = blockIdx.y;
    const int r0 = blockIdx.x * 128;

    const float* qp = g_q + ((size_t)bh * 1024 + r0) * 64;
    const float* kbase = g_k + (size_t)bh * 65536;
    const float* vtb = g_v + (size_t)bh * 65536;   // [64][1024]

    // prologue: Q (128x16 atoms) + chunk0 K/V^T (64x16 atoms each)
#pragma unroll
    for (int i = 0; i < 8; i++) {
        int a = i * 256 + tid;
        int row = a >> 4, k4 = a & 15;
        cp16(qk_addr(sb + AQ_OFF, row, k4), qp + (size_t)row * 64 + k4 * 4);
    }
#pragma unroll
    for (int i = 0; i < 4; i++) {
        int a = i * 256 + tid;
        int row = a >> 4, k4 = a & 15;
        cp16(qk_addr(sb + AK_OFF, row, k4), kbase + (size_t)row * 64 + k4 * 4);
        cp16(qk_addr(sb + AV_OFF, row, k4), vtb + (size_t)row * 1024 + k4 * 4);
    }
    CP_COMMIT();

    float o[8][4];
    float m0v = -1e30f, m1v = -1e30f, l0 = 0.f, l1 = 0.f;
#pragma unroll
    for (int j = 0; j < 8; j++)
#pragma unroll
        for (int q = 0; q < 4; q++) o[j][q] = 0.f;

    const int a_l15 = lane & 15, a_lhi = lane >> 4;
    const int b_row_in = (lane & 7) + ((lane >> 4) << 3);
    const int b_k_sel = (lane >> 3) & 1;
    const int lsA = (lane & ~3) + (t4 >> 1);       // P-shuffle source lanes
    const int lsB = lsA + 2;
    const bool odd = (t4 & 1);

    for (int c = 0; c < 16; c++) {
        __syncthreads();
        if (c + 1 < 16) {
            const uint32_t kb2 = sb + AK_OFF + ((c + 1) & 1) * 16384;
            const uint32_t vb2 = sb + AV_OFF + ((c + 1) & 1) * 16384;
            const float* ksrc = kbase + (size_t)(c + 1) * 4096;
            const float* vsrc = vtb + (size_t)(c + 1) * 64;
#pragma unroll
            for (int i = 0; i < 4; i++) {
                int a = i * 256 + tid;
                int row = a >> 4, k4 = a & 15;
                cp16(qk_addr(kb2, row, k4), ksrc + (size_t)row * 64 + k4 * 4);
                cp16(qk_addr(vb2, row, k4), vsrc + (size_t)row * 1024 + k4 * 4);
            }
        }
        CP_COMMIT();
        CP_WAIT1();
        __syncthreads();

        const uint32_t kb = sb + AK_OFF + (c & 1) * 16384;
        const uint32_t vb = sb + AV_OFF + (c & 1) * 16384;

        // ---- S = Q @ K^T (Q pre-scaled) ----
        float s[8][4];
#pragma unroll
        for (int j = 0; j < 8; j++)
#pragma unroll
            for (int q = 0; q < 4; q++) s[j][q] = 0.f;
#pragma unroll
        for (int ks = 0; ks < 8; ks++) {
            uint32_t ar[4];
            {
                int row = w * 16 + a_l15;
                int k4 = ks * 2 + a_lhi;
                ldsm4(ar[0], ar[1], ar[2], ar[3], qk_addr(sb + AQ_OFF, row, k4));
            }
#pragma unroll
            for (int p = 0; p < 4; p++) {
                int row = p * 16 + b_row_in;
                int k4 = ks * 2 + b_k_sel;
                uint32_t r0b, r1b, r2b, r3b;
                ldsm4(r0b, r1b, r2b, r3b, qk_addr(kb, row, k4));
                mma_tf32(s[2 * p], ar, r0b, r1b);
                mma_tf32(s[2 * p + 1], ar, r2b, r3b);
            }
        }

        // ---- online softmax; exp outputs rounded to tf32 for P ----
        float mx0 = -1e30f, mx1 = -1e30f;
#pragma unroll
        for (int j = 0; j < 8; j++) {
            mx0 = fmaxf(mx0, fmaxf(s[j][0], s[j][1]));
            mx1 = fmaxf(mx1, fmaxf(s[j][2], s[j][3]));
        }
        mx0 = fmaxf(mx0, __shfl_xor_sync(0xffffffffu, mx0, 1));
        mx0 = fmaxf(mx0, __shfl_xor_sync(0xffffffffu, mx0, 2));
        mx1 = fmaxf(mx1, __shfl_xor_sync(0xffffffffu, mx1, 1));
        mx1 = fmaxf(mx1, __shfl_xor_sync(0xffffffffu, mx1, 2));
        const float mn0 = fmaxf(m0v, mx0), mn1 = fmaxf(m1v, mx1);
        float sum0 = 0.f, sum1 = 0.f;
#pragma unroll
        for (int j = 0; j < 8; j++) {
            s[j][0] = rtf(__expf(s[j][0] - mn0));
            s[j][1] = rtf(__expf(s[j][1] - mn0));
            s[j][2] = rtf(__expf(s[j][2] - mn1));
            s[j][3] = rtf(__expf(s[j][3] - mn1));
            sum0 += s[j][0] + s[j][1];
            sum1 += s[j][2] + s[j][3];
        }
        sum0 += __shfl_xor_sync(0xffffffffu, sum0, 1);
        sum0 += __shfl_xor_sync(0xffffffffu, sum0, 2);
        sum1 += __shfl_xor_sync(0xffffffffu, sum1, 1);
        sum1 += __shfl_xor_sync(0xffffffffu, sum1, 2);
        const float al0 = __expf(m0v - mn0), al1 = __expf(m1v - mn1);
        l0 = l0 * al0 + sum0; l1 = l1 * al1 + sum1;
        m0v = mn0; m1v = mn1;
#pragma unroll
        for (int j = 0; j < 8; j++) {
            o[j][0] *= al0; o[j][1] *= al0;
            o[j][2] *= al1; o[j][3] *= al1;
        }

        // ---- O += P @ V : P accum->A-frag via shuffles, V^T via ldmatrix ----
#pragma unroll
        for (int kk = 0; kk < 8; kk++) {
            const float u0 = __shfl_sync(0xffffffffu, s[kk][0], lsA);
            const float u1 = __shfl_sync(0xffffffffu, s[kk][1], lsA);
            const float u2 = __shfl_sync(0xffffffffu, s[kk][2], lsA);
            const float u3 = __shfl_sync(0xffffffffu, s[kk][3], lsA);
            const float w0 = __shfl_sync(0xffffffffu, s[kk][0], lsB);
            const float w1 = __shfl_sync(0xffffffffu, s[kk][1], lsB);
            const float w2 = __shfl_sync(0xffffffffu, s[kk][2], lsB);
            const float w3 = __shfl_sync(0xffffffffu, s[kk][3], lsB);
            uint32_t pa[4];
            pa[0] = __float_as_uint(odd ? u1 : u0);
            pa[1] = __float_as_uint(odd ? u3 : u2);
            pa[2] = __float_as_uint(odd ? w1 : w0);
            pa[3] = __float_as_uint(odd ? w3 : w2);
#pragma unroll
            for (int p = 0; p < 4; p++) {
                int row = p * 16 + b_row_in;        // d-dim
                int k4 = kk * 2 + b_k_sel;          // key-dim atoms
                uint32_t r0b, r1b, r2b, r3b;
                ldsm4(r0b, r1b, r2b, r3b, qk_addr(vb, row, k4));
                mma_tf32(o[2 * p], pa, r0b, r1b);
                mma_tf32(o[2 * p + 1], pa, r2b, r3b);
            }
        }
    }

    // epilogue -> g_ao [B*N][768], tf32-rounded for proj consumption
    const int b = bh / HEADS, h = bh % HEADS;
    const float i0 = 1.0f / l0, i1 = 1.0f / l1;
    const int na = r0 + w * 16 + g;
#pragma unroll
    for (int j = 0; j < 8; j++) {
        const int col = h * 64 + j * 8 + t4 * 2;
        *(float2*)(g_ao + ((size_t)(b * 1024 + na)) * DIMK + col) =
            make_float2(rtf(o[j][0] * i0), rtf(o[j][1] * i0));
        *(float2*)(g_ao + ((size_t)(b * 1024 + na + 8)) * DIMK + col) =
            make_float2(rtf(o[j][2] * i1), rtf(o[j][3] * i1));
    }
}

// ---------------- launch ----------------
extern "C" void kernel_launch(void* const* d_in, const int* in_sizes, int n_in,
                              void* d_out, int out_size)
{
    const float* x      = (const float*)d_in[0];
    const float* qkv_w  = (const float*)d_in[1];
    const float* qkv_b  = (const float*)d_in[2];
    // d_in[3] = qkv_B (unused feedback-alignment buffer)
    const float* proj_w = (const float*)d_in[4];
    const float* proj_b = (const float*)d_in[5];
    // d_in[6] = proj_B (unused)
    float* out = (float*)d_out;

    cudaFuncSetAttribute(gemm_qkv_mm, cudaFuncAttributeMaxDynamicSharedMemorySize, GSM_TOTAL);
    cudaFuncSetAttribute(gemm_proj_mm, cudaFuncAttributeMaxDynamicSharedMemorySize, GSM_TOTAL);
    cudaFuncSetAttribute(attn_mm, cudaFuncAttributeMaxDynamicSharedMemorySize, ASM_TOTAL);

    float* xr; float* wq; float* wp;
    cudaGetSymbolAddress((void**)&xr, g_xr);
    cudaGetSymbolAddress((void**)&wq, g_wq);
    cudaGetSymbolAddress((void**)&wp, g_wp);

    preround_k<<<12288, 256>>>((const float4*)x, (float4*)xr, 3145728);
    preround_k<<<1728, 256>>>((const float4*)qkv_w, (float4*)wq, 442368);
    preround_k<<<576, 256>>>((const float4*)proj_w, (float4*)wp, 147456);

    gemm_qkv_mm<<<dim3(18, 128), 256, GSM_TOTAL>>>(qkv_b);
    attn_mm<<<dim3(8, 192), 256, ASM_TOTAL>>>();
    gemm_proj_mm<<<dim3(6, 128), 256, GSM_TOTAL>>>(proj_b, out);
}

// round 9
// speedup vs baseline: 4.3313x; 1.0690x over previous
#include <cuda_runtime.h>
#include <cstdint>
#include <math.h>

// Shapes (fixed): B=16, N=1024, C=768, H=12, hd=64
#define DIMK 768
#define HEADS 12

// ---------------- scratch (no cudaMalloc allowed) ----------------
__device__ __align__(16) float g_q[12582912];   // [B*H][1024][64], tf32-rounded, pre-scaled
__device__ __align__(16) float g_k[12582912];   // [B*H][1024][64], tf32-rounded
__device__ __align__(16) float g_v[12582912];   // [B*H][64][1024]  V^T, tf32-rounded
__device__ __align__(16) float g_ao[12582912];  // [B*N][768] attn out, tf32-rounded
__device__ __align__(16) float g_xr[12582912];  // X pre-rounded to tf32
__device__ __align__(16) float g_wq[1769472];   // qkv_w pre-rounded
__device__ __align__(16) float g_wp[589824];    // proj_w pre-rounded

// ---------------- PTX helpers ----------------
__device__ __forceinline__ uint32_t smem_u32(const void* p) {
    uint32_t a;
    asm("{ .reg .u64 t; cvta.to.shared.u64 t, %1; cvt.u32.u64 %0, t; }" : "=r"(a) : "l"(p));
    return a;
}
__device__ __forceinline__ void cp16(uint32_t dst, const void* src) {
    asm volatile("cp.async.cg.shared.global [%0], [%1], 16;" :: "r"(dst), "l"(src));
}
#define CP_COMMIT() asm volatile("cp.async.commit_group;" ::: "memory")
#define CP_WAIT1()  asm volatile("cp.async.wait_group 1;" ::: "memory")

__device__ __forceinline__ void ldsm4(uint32_t& r0, uint32_t& r1, uint32_t& r2, uint32_t& r3,
                                      uint32_t addr) {
    asm volatile("ldmatrix.sync.aligned.m8n8.x4.shared.b16 {%0,%1,%2,%3}, [%4];"
                 : "=r"(r0), "=r"(r1), "=r"(r2), "=r"(r3) : "r"(addr));
}
__device__ __forceinline__ uint32_t f2tf(float f) {
    uint32_t r;
    asm volatile("cvt.rna.tf32.f32 %0, %1;" : "=r"(r) : "f"(f));
    return r;
}
__device__ __forceinline__ float rtf(float f) { return __uint_as_float(f2tf(f)); }
__device__ __forceinline__ void mma_tf32(float c[4], const uint32_t a[4],
                                         uint32_t b0, uint32_t b1) {
    asm volatile("mma.sync.aligned.m16n8k8.row.col.f32.tf32.tf32.f32 "
                 "{%0,%1,%2,%3}, {%4,%5,%6,%7}, {%8,%9}, {%0,%1,%2,%3};"
                 : "+f"(c[0]), "+f"(c[1]), "+f"(c[2]), "+f"(c[3])
                 : "r"(a[0]), "r"(a[1]), "r"(a[2]), "r"(a[3]), "r"(b0), "r"(b1));
}

// ---------------- pre-round to tf32 ----------------
__global__ void preround_k(const float4* __restrict__ s, float4* __restrict__ d, int n4)
{
    int i = blockIdx.x * blockDim.x + threadIdx.x;
    if (i < n4) {
        float4 v = s[i];
        v.x = rtf(v.x); v.y = rtf(v.y); v.z = rtf(v.z); v.w = rtf(v.w);
        d[i] = v;
    }
}

// ======================= GEMM (mma.sync tf32, operands pre-rounded) =======================
// C[m][n] = sum_k A[m][k] * W[n][k]. BM=128 BN=128 BK=32, 128 thr (4 warps 2x2),
// warp tile 64x64. Smem: 16B atoms, atom (row,k4) at row*128 + ((k4^row&7)<<4).
#define GSTG_BYTES 32768
#define GSM_TOTAL (3 * GSTG_BYTES)

__device__ __forceinline__ void g_load_stage(uint32_t sbase, const float* __restrict__ Ag,
                                             const float* __restrict__ Bg, int kt, int tid)
{
    const int kof = kt * 32;
#pragma unroll
    for (int i = 0; i < 8; i++) {
        int a = i * 128 + tid;
        int row = a >> 3, k4 = a & 7;
        cp16(sbase + row * 128 + (((k4 ^ row) & 7) << 4),
             Ag + (size_t)row * DIMK + kof + k4 * 4);
    }
#pragma unroll
    for (int i = 0; i < 8; i++) {
        int a = i * 128 + tid;
        int row = a >> 3, k4 = a & 7;
        cp16(sbase + 16384 + row * 128 + (((k4 ^ row) & 7) << 4),
             Bg + (size_t)row * DIMK + kof + k4 * 4);
    }
}

__device__ __forceinline__ void g_compute(uint32_t abase, uint32_t bbase,
                                          float acc[4][8][4], int lane, int wm, int wn)
{
    const int l15 = lane & 15;
    const int lhi = lane >> 4;
    const int brow_in = (lane & 7) + ((lane >> 4) << 3);
    const int bk_sel = (lane >> 3) & 1;
#pragma unroll
    for (int ks = 0; ks < 4; ks++) {
        uint32_t ar[4][4];
#pragma unroll
        for (int i = 0; i < 4; i++) {
            int row = wm * 64 + i * 16 + l15;
            int k4 = ks * 2 + lhi;
            ldsm4(ar[i][0], ar[i][1], ar[i][2], ar[i][3],
                  abase + row * 128 + (((k4 ^ row) & 7) << 4));
        }
        uint32_t br[8][2];
#pragma unroll
        for (int p = 0; p < 4; p++) {
            int row = wn * 64 + p * 16 + brow_in;
            int k4 = ks * 2 + bk_sel;
            uint32_t r0, r1, r2, r3;
            ldsm4(r0, r1, r2, r3, bbase + row * 128 + (((k4 ^ row) & 7) << 4));
            br[2 * p][0] = r0; br[2 * p][1] = r1;
            br[2 * p + 1][0] = r2; br[2 * p + 1][1] = r3;
        }
#pragma unroll
        for (int i = 0; i < 4; i++)
#pragma unroll
            for (int j = 0; j < 8; j++)
                mma_tf32(acc[i][j], ar[i], br[j][0], br[j][1]);
    }
}

#define GEMM_MAIN(Ag, Bg)                                                        \
    extern __shared__ char smem[];                                               \
    const uint32_t sb = smem_u32(smem);                                          \
    const int tid = threadIdx.x, lane = tid & 31, wid = tid >> 5;                \
    const int wm = wid & 1, wn = wid >> 1;                                       \
    float acc[4][8][4];                                                          \
    _Pragma("unroll") for (int i = 0; i < 4; i++)                                \
        _Pragma("unroll") for (int j = 0; j < 8; j++)                            \
            _Pragma("unroll") for (int q = 0; q < 4; q++) acc[i][j][q] = 0.f;    \
    g_load_stage(sb, Ag, Bg, 0, tid); CP_COMMIT();                               \
    g_load_stage(sb + GSTG_BYTES, Ag, Bg, 1, tid); CP_COMMIT();                  \
    for (int kt = 0; kt < 24; kt++) {                                            \
        CP_WAIT1();                                                              \
        __syncthreads();                                                         \
        if (kt + 2 < 24)                                                         \
            g_load_stage(sb + ((kt + 2) % 3) * GSTG_BYTES, Ag, Bg, kt + 2, tid); \
        CP_COMMIT();                                                             \
        uint32_t st = sb + (kt % 3) * GSTG_BYTES;                                \
        g_compute(st, st + 16384, acc, lane, wm, wn);                            \
    }

__global__ __launch_bounds__(128, 2)
void gemm_qkv_mm(const float* __restrict__ bias)
{
    const int m0 = blockIdx.y * 128;
    const int n0 = blockIdx.x * 128;
    GEMM_MAIN(g_xr + (size_t)m0 * DIMK, g_wq + (size_t)n0 * DIMK)

    // epilogue: scatter to g_q/g_k (row-major) or g_v (transposed); tf32-rounded
    const int g = lane >> 2, t4 = lane & 3;
    const int cb = n0 + wn * 64;
    const int which = cb / 768;            // 0=q 1=k 2=v
    const int h = (cb % 768) / 64;
    if (which < 2) {
        const float scale = (which == 0) ? 0.125f : 1.0f;
        float* dst = (which == 0) ? g_q : g_k;
#pragma unroll
        for (int i = 0; i < 4; i++) {
#pragma unroll
            for (int j = 0; j < 8; j++) {
                const int col = j * 8 + t4 * 2;
                const float2 bv = *(const float2*)(bias + cb + col);
                int m = m0 + wm * 64 + i * 16 + g;
                int b = m >> 10, n = m & 1023;
                float2 v0 = make_float2(rtf((acc[i][j][0] + bv.x) * scale),
                                        rtf((acc[i][j][1] + bv.y) * scale));
                *(float2*)(dst + ((size_t)(b * HEADS + h) * 1024 + n) * 64 + col) = v0;
                m += 8; b = m >> 10; n = m & 1023;
                float2 v1 = make_float2(rtf((acc[i][j][2] + bv.x) * scale),
                                        rtf((acc[i][j][3] + bv.y) * scale));
                *(float2*)(dst + ((size_t)(b * HEADS + h) * 1024 + n) * 64 + col) = v1;
            }
        }
    } else {
        // V^T: g_v[bh][d][1024]
#pragma unroll
        for (int i = 0; i < 4; i++) {
#pragma unroll
            for (int j = 0; j < 8; j++) {
                const int col = j * 8 + t4 * 2;
                const float2 bv = *(const float2*)(bias + cb + col);
                int m = m0 + wm * 64 + i * 16 + g;
                int b = m >> 10, n = m & 1023;
                size_t base = (size_t)(b * HEADS + h) * 65536;
                g_v[base + (size_t)(col + 0) * 1024 + n] = rtf(acc[i][j][0] + bv.x);
                g_v[base + (size_t)(col + 1) * 1024 + n] = rtf(acc[i][j][1] + bv.y);
                m += 8; b = m >> 10; n = m & 1023;
                base = (size_t)(b * HEADS + h) * 65536;
                g_v[base + (size_t)(col + 0) * 1024 + n] = rtf(acc[i][j][2] + bv.x);
                g_v[base + (size_t)(col + 1) * 1024 + n] = rtf(acc[i][j][3] + bv.y);
            }
        }
    }
}

__global__ __launch_bounds__(128, 2)
void gemm_proj_mm(const float* __restrict__ bias, float* __restrict__ out)
{
    const int m0 = blockIdx.y * 128;
    const int n0 = blockIdx.x * 128;
    GEMM_MAIN(g_ao + (size_t)m0 * DIMK, g_wp + (size_t)n0 * DIMK)

    const int g = lane >> 2, t4 = lane & 3;
#pragma unroll
    for (int i = 0; i < 4; i++) {
#pragma unroll
        for (int j = 0; j < 8; j++) {
            const int col = n0 + wn * 64 + j * 8 + t4 * 2;
            const float2 bv = *(const float2*)(bias + col);
            const int m = m0 + wm * 64 + i * 16 + g;
            *(float2*)(out + (size_t)m * DIMK + col) =
                make_float2(acc[i][j][0] + bv.x, acc[i][j][1] + bv.y);
            *(float2*)(out + (size_t)(m + 8) * DIMK + col) =
                make_float2(acc[i][j][2] + bv.x, acc[i][j][3] + bv.y);
        }
    }
}

// ======================= Flash attention (mma.sync tf32) =======================
// 128 thr (4 warps), Br=128 (32 rows/warp: 2 m16 blocks), Bc=64, d=64.
// Q: 128 rows x 256B swizzled. K: [key][64] rows. V^T: [d][key] rows (same layout).
// P transposed accum->A-frag via register shuffles (no smem).
#define AQ_OFF 0                 // 32768
#define AK_OFF 32768             // 2 x 16384
#define AV_OFF 65536             // 2 x 16384
#define ASM_TOTAL 98304

__device__ __forceinline__ uint32_t qk_addr(uint32_t base, int row, int k4) {
    return base + row * 256 + ((((k4 & 8) | ((k4 ^ row) & 7))) << 4);
}

__global__ __launch_bounds__(128, 2)
void attn_mm()
{
    extern __shared__ char smem[];
    const uint32_t sb = smem_u32(smem);

    const int tid = threadIdx.x, lane = tid & 31, w = tid >> 5;
    const int g = lane >> 2, t4 = lane & 3;
    const int bh = blockIdx.y;
    const int r0 = blockIdx.x * 128;

    const float* qp = g_q + ((size_t)bh * 1024 + r0) * 64;
    const float* kbase = g_k + (size_t)bh * 65536;
    const float* vtb = g_v + (size_t)bh * 65536;   // [64][1024]

    // prologue: Q (128x16 atoms) + chunk0 K/V^T (64x16 atoms each)
#pragma unroll
    for (int i = 0; i < 16; i++) {
        int a = i * 128 + tid;
        int row = a >> 4, k4 = a & 15;
        cp16(qk_addr(sb + AQ_OFF, row, k4), qp + (size_t)row * 64 + k4 * 4);
    }
#pragma unroll
    for (int i = 0; i < 8; i++) {
        int a = i * 128 + tid;
        int row = a >> 4, k4 = a & 15;
        cp16(qk_addr(sb + AK_OFF, row, k4), kbase + (size_t)row * 64 + k4 * 4);
        cp16(qk_addr(sb + AV_OFF, row, k4), vtb + (size_t)row * 1024 + k4 * 4);
    }
    CP_COMMIT();

    float o[2][8][4];
    float m_run[2][2], l_run[2][2];
#pragma unroll
    for (int i = 0; i < 2; i++) {
        m_run[i][0] = -1e30f; m_run[i][1] = -1e30f;
        l_run[i][0] = 0.f;    l_run[i][1] = 0.f;
#pragma unroll
        for (int j = 0; j < 8; j++)
#pragma unroll
            for (int q = 0; q < 4; q++) o[i][j][q] = 0.f;
    }

    const int a_l15 = lane & 15, a_lhi = lane >> 4;
    const int b_row_in = (lane & 7) + ((lane >> 4) << 3);
    const int b_k_sel = (lane >> 3) & 1;
    const int lsA = (lane & ~3) + (t4 >> 1);       // P-shuffle source lanes
    const int lsB = lsA + 2;
    const bool odd = (t4 & 1);

    for (int c = 0; c < 16; c++) {
        __syncthreads();
        if (c + 1 < 16) {
            const uint32_t kb2 = sb + AK_OFF + ((c + 1) & 1) * 16384;
            const uint32_t vb2 = sb + AV_OFF + ((c + 1) & 1) * 16384;
            const float* ksrc = kbase + (size_t)(c + 1) * 4096;
            const float* vsrc = vtb + (size_t)(c + 1) * 64;
#pragma unroll
            for (int i = 0; i < 8; i++) {
                int a = i * 128 + tid;
                int row = a >> 4, k4 = a & 15;
                cp16(qk_addr(kb2, row, k4), ksrc + (size_t)row * 64 + k4 * 4);
                cp16(qk_addr(vb2, row, k4), vsrc + (size_t)row * 1024 + k4 * 4);
            }
        }
        CP_COMMIT();
        CP_WAIT1();
        __syncthreads();

        const uint32_t kb = sb + AK_OFF + (c & 1) * 16384;
        const uint32_t vb = sb + AV_OFF + (c & 1) * 16384;

        // ---- S = Q @ K^T (Q pre-scaled) ----
        float s[2][8][4];
#pragma unroll
        for (int i = 0; i < 2; i++)
#pragma unroll
            for (int j = 0; j < 8; j++)
#pragma unroll
                for (int q = 0; q < 4; q++) s[i][j][q] = 0.f;
#pragma unroll
        for (int ks = 0; ks < 8; ks++) {
            uint32_t ar[2][4];
#pragma unroll
            for (int i = 0; i < 2; i++) {
                int row = w * 32 + i * 16 + a_l15;
                int k4 = ks * 2 + a_lhi;
                ldsm4(ar[i][0], ar[i][1], ar[i][2], ar[i][3], qk_addr(sb + AQ_OFF, row, k4));
            }
#pragma unroll
            for (int p = 0; p < 4; p++) {
                int row = p * 16 + b_row_in;
                int k4 = ks * 2 + b_k_sel;
                uint32_t r0b, r1b, r2b, r3b;
                ldsm4(r0b, r1b, r2b, r3b, qk_addr(kb, row, k4));
#pragma unroll
                for (int i = 0; i < 2; i++) {
                    mma_tf32(s[i][2 * p], ar[i], r0b, r1b);
                    mma_tf32(s[i][2 * p + 1], ar[i], r2b, r3b);
                }
            }
        }

        // ---- online softmax per m16 block; exp outputs rounded to tf32 for P ----
#pragma unroll
        for (int i = 0; i < 2; i++) {
            float mx0 = -1e30f, mx1 = -1e30f;
#pragma unroll
            for (int j = 0; j < 8; j++) {
                mx0 = fmaxf(mx0, fmaxf(s[i][j][0], s[i][j][1]));
                mx1 = fmaxf(mx1, fmaxf(s[i][j][2], s[i][j][3]));
            }
            mx0 = fmaxf(mx0, __shfl_xor_sync(0xffffffffu, mx0, 1));
            mx0 = fmaxf(mx0, __shfl_xor_sync(0xffffffffu, mx0, 2));
            mx1 = fmaxf(mx1, __shfl_xor_sync(0xffffffffu, mx1, 1));
            mx1 = fmaxf(mx1, __shfl_xor_sync(0xffffffffu, mx1, 2));
            const float mn0 = fmaxf(m_run[i][0], mx0), mn1 = fmaxf(m_run[i][1], mx1);
            float sum0 = 0.f, sum1 = 0.f;
#pragma unroll
            for (int j = 0; j < 8; j++) {
                s[i][j][0] = rtf(__expf(s[i][j][0] - mn0));
                s[i][j][1] = rtf(__expf(s[i][j][1] - mn0));
                s[i][j][2] = rtf(__expf(s[i][j][2] - mn1));
                s[i][j][3] = rtf(__expf(s[i][j][3] - mn1));
                sum0 += s[i][j][0] + s[i][j][1];
                sum1 += s[i][j][2] + s[i][j][3];
            }
            sum0 += __shfl_xor_sync(0xffffffffu, sum0, 1);
            sum0 += __shfl_xor_sync(0xffffffffu, sum0, 2);
            sum1 += __shfl_xor_sync(0xffffffffu, sum1, 1);
            sum1 += __shfl_xor_sync(0xffffffffu, sum1, 2);
            const float al0 = __expf(m_run[i][0] - mn0), al1 = __expf(m_run[i][1] - mn1);
            l_run[i][0] = l_run[i][0] * al0 + sum0;
            l_run[i][1] = l_run[i][1] * al1 + sum1;
            m_run[i][0] = mn0; m_run[i][1] = mn1;
#pragma unroll
            for (int j = 0; j < 8; j++) {
                o[i][j][0] *= al0; o[i][j][1] *= al0;
                o[i][j][2] *= al1; o[i][j][3] *= al1;
            }
        }

        // ---- O += P @ V : P accum->A-frag via shuffles, V^T via ldmatrix ----
#pragma unroll
        for (int kk = 0; kk < 8; kk++) {
            uint32_t vr[8][2];
#pragma unroll
            for (int p = 0; p < 4; p++) {
                int row = p * 16 + b_row_in;        // d-dim
                int k4 = kk * 2 + b_k_sel;          // key-dim atoms
                uint32_t r0b, r1b, r2b, r3b;
                ldsm4(r0b, r1b, r2b, r3b, qk_addr(vb, row, k4));
                vr[2 * p][0] = r0b; vr[2 * p][1] = r1b;
                vr[2 * p + 1][0] = r2b; vr[2 * p + 1][1] = r3b;
            }
#pragma unroll
            for (int i = 0; i < 2; i++) {
                const float u0 = __shfl_sync(0xffffffffu, s[i][kk][0], lsA);
                const float u1 = __shfl_sync(0xffffffffu, s[i][kk][1], lsA);
                const float u2 = __shfl_sync(0xffffffffu, s[i][kk][2], lsA);
                const float u3 = __shfl_sync(0xffffffffu, s[i][kk][3], lsA);
                const float w0 = __shfl_sync(0xffffffffu, s[i][kk][0], lsB);
                const float w1 = __shfl_sync(0xffffffffu, s[i][kk][1], lsB);
                const float w2 = __shfl_sync(0xffffffffu, s[i][kk][2], lsB);
                const float w3 = __shfl_sync(0xffffffffu, s[i][kk][3], lsB);
                uint32_t pa[4];
                pa[0] = __float_as_uint(odd ? u1 : u0);
                pa[1] = __float_as_uint(odd ? u3 : u2);
                pa[2] = __float_as_uint(odd ? w1 : w0);
                pa[3] = __float_as_uint(odd ? w3 : w2);
#pragma unroll
                for (int j = 0; j < 8; j++)
                    mma_tf32(o[i][j], pa, vr[j][0], vr[j][1]);
            }
        }
    }

    // epilogue -> g_ao [B*N][768], tf32-rounded for proj consumption
    const int b = bh / HEADS, h = bh % HEADS;
#pragma unroll
    for (int i = 0; i < 2; i++) {
        const float i0 = 1.0f / l_run[i][0], i1 = 1.0f / l_run[i][1];
        const int na = r0 + w * 32 + i * 16 + g;
#pragma unroll
        for (int j = 0; j < 8; j++) {
            const int col = h * 64 + j * 8 + t4 * 2;
            *(float2*)(g_ao + ((size_t)(b * 1024 + na)) * DIMK + col) =
                make_float2(rtf(o[i][j][0] * i0), rtf(o[i][j][1] * i0));
            *(float2*)(g_ao + ((size_t)(b * 1024 + na + 8)) * DIMK + col) =
                make_float2(rtf(o[i][j][2] * i1), rtf(o[i][j][3] * i1));
        }
    }
}

// ---------------- launch ----------------
extern "C" void kernel_launch(void* const* d_in, const int* in_sizes, int n_in,
                              void* d_out, int out_size)
{
    const float* x      = (const float*)d_in[0];
    const float* qkv_w  = (const float*)d_in[1];
    const float* qkv_b  = (const float*)d_in[2];
    // d_in[3] = qkv_B (unused feedback-alignment buffer)
    const float* proj_w = (const float*)d_in[4];
    const float* proj_b = (const float*)d_in[5];
    // d_in[6] = proj_B (unused)
    float* out = (float*)d_out;

    cudaFuncSetAttribute(gemm_qkv_mm, cudaFuncAttributeMaxDynamicSharedMemorySize, GSM_TOTAL);
    cudaFuncSetAttribute(gemm_proj_mm, cudaFuncAttributeMaxDynamicSharedMemorySize, GSM_TOTAL);
    cudaFuncSetAttribute(attn_mm, cudaFuncAttributeMaxDynamicSharedMemorySize, ASM_TOTAL);

    float* xr; float* wq; float* wp;
    cudaGetSymbolAddress((void**)&xr, g_xr);
    cudaGetSymbolAddress((void**)&wq, g_wq);
    cudaGetSymbolAddress((void**)&wp, g_wp);

    preround_k<<<12288, 256>>>((const float4*)x, (float4*)xr, 3145728);
    preround_k<<<1728, 256>>>((const float4*)qkv_w, (float4*)wq, 442368);
    preround_k<<<576, 256>>>((const float4*)proj_w, (float4*)wp, 147456);

    gemm_qkv_mm<<<dim3(18, 128), 128, GSM_TOTAL>>>(qkv_b);
    attn_mm<<<dim3(8, 192), 128, ASM_TOTAL>>>();
    gemm_proj_mm<<<dim3(6, 128), 128, GSM_TOTAL>>>(proj_b, out);
}